// round 16
// baseline (speedup 1.0000x reference)
#include <cuda_runtime.h>
#include <cuda_bf16.h>
#include <math.h>
#include <stdint.h>

#define BATCH 8
#define CDIM  128
#define NPIX  4096
#define TEN   (BATCH*CDIM*NPIX)

// ---------------- scratch ----------------------------------------------------
__device__ float g_bufA[TEN];
__device__ float g_bufB[TEN];
__device__ float g_bufC[TEN];
__device__ float g_bufD[TEN];
__device__ float g_qkv[BATCH * 640 * NPIX];
__device__ uint32_t g_xhi[BATCH * 64 * NPIX];
__device__ uint32_t g_xlo[BATCH * 64 * NPIX];
__device__ uint32_t g_yhi[BATCH * 256 * NPIX];
__device__ uint32_t g_ylo[BATCH * 256 * NPIX];
__device__ uint32_t g_whi[131072];
__device__ uint32_t g_wlo[131072];
__device__ float g_m[BATCH * CDIM];
__device__ float g_gnpart[65536];
__device__ unsigned int g_cnt[8];          // per-batch completion counters (self-resetting)
__device__ float g_stats1[16];
__device__ float g_stats2[16];
__device__ float g_cpe_w[CDIM * 9];
__device__ float g_cpe_b[CDIM];

#define WOFF_ACTP 0
#define WOFF_INP  8192
#define WOFF_QKV  16384
#define WOFF_OUTP 57344
#define WOFF_MLP1 65536
#define WOFF_MLP2 98304

#define ATTN_SMEM 49152
#define GEMM_STAGE_U32 6656
#define GEMM_SMEM (GEMM_STAGE_U32 * 3 * 4)

// ---------------- helpers ----------------------------------------------------
__device__ __forceinline__ void pack2_hi_lo(float a, float b,
                                            uint32_t& hi, uint32_t& lo) {
    __nv_bfloat16 ha = __float2bfloat16_rn(a);
    __nv_bfloat16 hb = __float2bfloat16_rn(b);
    float ra = a - __bfloat162float(ha);
    float rb = b - __bfloat162float(hb);
    __nv_bfloat162 hv = __nv_bfloat162(ha, hb);
    __nv_bfloat162 lv = __floats2bfloat162_rn(ra, rb);
    hi = *(uint32_t*)&hv;
    lo = *(uint32_t*)&lv;
}

__device__ __forceinline__ void mma_bf16(float* d, const uint32_t* a, const uint32_t* b) {
    asm volatile(
        "mma.sync.aligned.m16n8k16.row.col.f32.bf16.bf16.f32 "
        "{%0,%1,%2,%3}, {%4,%5,%6,%7}, {%8,%9}, {%0,%1,%2,%3};"
        : "+f"(d[0]), "+f"(d[1]), "+f"(d[2]), "+f"(d[3])
        : "r"(a[0]), "r"(a[1]), "r"(a[2]), "r"(a[3]), "r"(b[0]), "r"(b[1]));
}

__device__ __forceinline__ void cp16(uint32_t* smem_dst, const uint32_t* gsrc) {
    uint32_t s = (uint32_t)__cvta_generic_to_shared(smem_dst);
    asm volatile("cp.async.cg.shared.global [%0], [%1], 16;" :: "r"(s), "l"(gsrc));
}

// ---------------- merged prep: wprep (blk 0-511) + gap (512-1535) + combine (1536)
__global__ void k_prep(const float* __restrict__ actp, const float* __restrict__ inp,
                       const float* __restrict__ qkv,  const float* __restrict__ outp,
                       const float* __restrict__ mlp1, const float* __restrict__ mlp2,
                       const float* __restrict__ x, float* __restrict__ m,
                       const float* __restrict__ wx, const float* __restrict__ bx,
                       const float* __restrict__ wy, const float* __restrict__ by) {
    int blk = blockIdx.x;
    if (blk < 512) {
        int gid = blk * 256 + threadIdx.x;
        const float* W; int O, C, base;
        if (gid < 8192)       { W = actp; O = 128; C = 128; base = WOFF_ACTP; }
        else if (gid < 16384) { W = inp;  O = 128; C = 128; base = WOFF_INP;  }
        else if (gid < 57344) { W = qkv;  O = 640; C = 128; base = WOFF_QKV;  }
        else if (gid < 65536) { W = outp; O = 128; C = 128; base = WOFF_OUTP; }
        else if (gid < 98304) { W = mlp1; O = 512; C = 128; base = WOFF_MLP1; }
        else                  { W = mlp2; O = 128; C = 512; base = WOFF_MLP2; }
        int idx = gid - base;
        int kp = idx / O, o = idx - kp * O;
        float a = W[(size_t)o * C + 2 * kp];
        float b = W[(size_t)o * C + 2 * kp + 1];
        uint32_t hi, lo;
        pack2_hi_lo(a, b, hi, lo);
        g_whi[base + idx] = hi;
        g_wlo[base + idx] = lo;
    } else if (blk < 1536) {
        int bc = blk - 512;
        const float4* p = (const float4*)(x + (size_t)bc * NPIX);
        float s = 0.f;
        for (int i = threadIdx.x; i < NPIX / 4; i += 256) {
            float4 v = p[i];
            s += v.x + v.y + v.z + v.w;
        }
        __shared__ float sm[256];
        sm[threadIdx.x] = s;
        __syncthreads();
        for (int st = 128; st > 0; st >>= 1) {
            if (threadIdx.x < st) sm[threadIdx.x] += sm[threadIdx.x + st];
            __syncthreads();
        }
        if (threadIdx.x == 0) m[bc] = sm[0] * (1.f / NPIX);
    } else {
        for (int i = threadIdx.x; i < CDIM * 9; i += 256) g_cpe_w[i] = wx[i] + wy[i];
        if (threadIdx.x < CDIM) g_cpe_b[threadIdx.x] = bx[threadIdx.x] + by[threadIdx.x];
    }
}

// ---------------- X preconversion ----------------------------------------------
template <int FLAGS>
__global__ void k_xprep(const float* __restrict__ X, const float* __restrict__ mulT,
                        uint32_t* __restrict__ Xhi, uint32_t* __restrict__ Xlo,
                        const float* __restrict__ stats,
                        const float* __restrict__ gam, const float* __restrict__ bet) {
    constexpr bool GN  = (FLAGS & 1) != 0;
    constexpr bool MUL = (FLAGS & 2) != 0;
    const int C = 128, c2n = 64;
    int gid = blockIdx.x * 256 + threadIdx.x;
    if (gid >= BATCH * c2n * 1024) return;
    int b = gid / (c2n * 1024);
    int r = gid - b * c2n * 1024;
    int c2 = r >> 10;
    int p4 = (r & 1023) << 2;
    int c0 = 2 * c2;

    const float* s0 = X + ((size_t)b * C + c0) * NPIX + p4;
    float4 a = *(const float4*)(s0);
    float4 d = *(const float4*)(s0 + NPIX);
    if (MUL) {
        const float* m0 = mulT + ((size_t)b * C + c0) * NPIX + p4;
        float4 u = *(const float4*)(m0);
        float4 v = *(const float4*)(m0 + NPIX);
        a.x *= u.x; a.y *= u.y; a.z *= u.z; a.w *= u.w;
        d.x *= v.x; d.y *= v.y; d.z *= v.z; d.w *= v.w;
    }
    if (GN) {
        float mu = stats[b], rs = stats[8 + b];
        float sc0 = gam[c0] * rs,     of0 = bet[c0] - mu * sc0;
        float sc1 = gam[c0 + 1] * rs, of1 = bet[c0 + 1] - mu * sc1;
        a.x = a.x * sc0 + of0; a.y = a.y * sc0 + of0;
        a.z = a.z * sc0 + of0; a.w = a.w * sc0 + of0;
        d.x = d.x * sc1 + of1; d.y = d.y * sc1 + of1;
        d.z = d.z * sc1 + of1; d.w = d.w * sc1 + of1;
    }
    uint4 h4, l4;
    pack2_hi_lo(a.x, d.x, h4.x, l4.x);
    pack2_hi_lo(a.y, d.y, h4.y, l4.y);
    pack2_hi_lo(a.z, d.z, h4.z, l4.z);
    pack2_hi_lo(a.w, d.w, h4.w, l4.w);
    size_t oi = ((size_t)b * c2n + c2) * NPIX + p4;
    *(uint4*)(Xhi + oi) = h4;
    *(uint4*)(Xlo + oi) = l4;
}

// ---------------- fused gate + eca + esa -----------------------------------------
__global__ void __launch_bounds__(256)
k_ecaesa(const float* __restrict__ x, const float* __restrict__ m,
         const float* __restrict__ eca_w, const float* __restrict__ alphaP,
         float* __restrict__ y) {
    __shared__ float msm[128], gates[128];
    __shared__ float pmax[4][64], pmin[4][64], sas[64];
    int bp = blockIdx.x;
    int b = bp >> 6;
    int p0 = (bp & 63) * 64;
    int tid = threadIdx.x;
    int pix = tid & 63, grp = tid >> 6;

    if (tid < 128) msm[tid] = m[b * 128 + tid];
    __syncthreads();
    if (tid < 128) {
        float s = 0.f;
#pragma unroll
        for (int t2 = 0; t2 < 5; t2++) {
            int cc = tid + t2 - 2;
            if (cc >= 0 && cc < 128) s += eca_w[t2] * msm[cc];
        }
        gates[tid] = 1.f / (1.f + __expf(-s));
    }

    const float* xp = x + (size_t)b * CDIM * NPIX + p0 + pix;
    float xv[32];
    float vmax = -1e30f, vmin = 1e30f;
#pragma unroll
    for (int i = 0; i < 32; i++) {
        int c = grp * 32 + i;
        float v = xp[(size_t)c * NPIX];
        xv[i] = v;
        float d = v - msm[c];
        vmax = fmaxf(vmax, d);
        vmin = fminf(vmin, d);
    }
    pmax[grp][pix] = vmax;
    pmin[grp][pix] = vmin;
    __syncthreads();
    if (tid < 64) {
        float a = alphaP[0];
        float mx = fmaxf(fmaxf(pmax[0][tid], pmax[1][tid]), fmaxf(pmax[2][tid], pmax[3][tid]));
        float mn = fminf(fminf(pmin[0][tid], pmin[1][tid]), fminf(pmin[2][tid], pmin[3][tid]));
        sas[tid] = a / (1.f + __expf(-mx)) + (1.f - a) / (1.f + __expf(-mn));
    }
    __syncthreads();
    float* yp = y + (size_t)b * CDIM * NPIX + p0 + pix;
    float sa = sas[pix];
#pragma unroll
    for (int i = 0; i < 32; i++) {
        int c = grp * 32 + i;
        yp[(size_t)c * NPIX] = xv[i] * (gates[c] + sa);
    }
}

// ---------------- depthwise 3x3, 4 outputs/thread; GNPART fuses the GN finalize ----
// GNPART=1: per-warp fp32 partials + last-block-per-batch reduces them to stats[]
// (threadfence-reduction pattern; deterministic summation order; counter self-resets)
template <int GNPART>
__global__ void k_dwconv4(const float* __restrict__ in, const float* __restrict__ wt,
                          const float* __restrict__ bs, float* __restrict__ out,
                          int mode, int cmul, int coff, int in_bstride,
                          float* __restrict__ part, float* __restrict__ stats) {
    int gid = blockIdx.x * blockDim.x + threadIdx.x;
    int p4 = gid & 1023;
    int c = (gid >> 10) & 127;
    int b = gid >> 17;
    int h = p4 >> 4, w4 = (p4 & 15) * 4;
    const float* ip = in + (size_t)b * in_bstride + (size_t)(c * cmul + coff) * NPIX;
    const float* wc = wt + c * 9;

    float acc0 = bs[c], acc1 = acc0, acc2 = acc0, acc3 = acc0;
    float ctr[4];

#pragma unroll
    for (int ky = 0; ky < 3; ky++) {
        int hh = h + ky - 1;
        if ((unsigned)hh < 64u) {
            const float* rp = ip + hh * 64;
            float4 cv = *(const float4*)(rp + w4);
            float lv = (w4 > 0) ? rp[w4 - 1] : 0.f;
            float rv = (w4 + 4 < 64) ? rp[w4 + 4] : 0.f;
            float v0 = lv, v1 = cv.x, v2 = cv.y, v3 = cv.z, v4 = cv.w, v5 = rv;
            float w0 = wc[ky * 3 + 0], w1 = wc[ky * 3 + 1], w2 = wc[ky * 3 + 2];
            acc0 += w0 * v0 + w1 * v1 + w2 * v2;
            acc1 += w0 * v1 + w1 * v2 + w2 * v3;
            acc2 += w0 * v2 + w1 * v3 + w2 * v4;
            acc3 += w0 * v3 + w1 * v4 + w2 * v5;
            if (ky == 1) { ctr[0] = v1; ctr[1] = v2; ctr[2] = v3; ctr[3] = v4; }
        }
    }
    if (mode == 1) { acc0 += ctr[0]; acc1 += ctr[1]; acc2 += ctr[2]; acc3 += ctr[3]; }
    if (mode == 2) {
        acc0 = fmaxf(acc0, 0.f); acc1 = fmaxf(acc1, 0.f);
        acc2 = fmaxf(acc2, 0.f); acc3 = fmaxf(acc3, 0.f);
    }
    *(float4*)(out + (size_t)gid * 4) = make_float4(acc0, acc1, acc2, acc3);

    if (GNPART) {
        float s = acc0 + acc1 + acc2 + acc3;
        float s2 = acc0 * acc0 + acc1 * acc1 + acc2 * acc2 + acc3 * acc3;
#pragma unroll
        for (int off = 16; off > 0; off >>= 1) {
            s  += __shfl_down_sync(0xffffffffu, s,  off);
            s2 += __shfl_down_sync(0xffffffffu, s2, off);
        }
        if ((threadIdx.x & 31) == 0) {
            int slot = blockIdx.x * 8 + (threadIdx.x >> 5);
            part[slot * 2]     = s;
            part[slot * 2 + 1] = s2;
        }
        // --- last block of this batch finalizes the GN stats in-kernel ---
        __shared__ unsigned int sLast;
        __shared__ float fs[8], fs2[8];
        int batch = blockIdx.x >> 9;             // 512 blocks per batch
        __threadfence();                          // release partials (gpu scope)
        __syncthreads();
        if (threadIdx.x == 0) {
            unsigned int old = atomicAdd(&g_cnt[batch], 1u);
            sLast = (old == 511u) ? 1u : 0u;
        }
        __syncthreads();
        if (sLast) {
            const float2* p = (const float2*)(part + batch * 8192);
            float rs = 0.f, rs2 = 0.f;
#pragma unroll
            for (int i = 0; i < 16; i++) {
                float2 v = p[threadIdx.x + i * 256];
                rs += v.x;
                rs2 += v.y;
            }
#pragma unroll
            for (int off = 16; off > 0; off >>= 1) {
                rs  += __shfl_down_sync(0xffffffffu, rs,  off);
                rs2 += __shfl_down_sync(0xffffffffu, rs2, off);
            }
            if ((threadIdx.x & 31) == 0) {
                fs[threadIdx.x >> 5] = rs;
                fs2[threadIdx.x >> 5] = rs2;
            }
            __syncthreads();
            if (threadIdx.x == 0) {
                double ds = 0.0, ds2 = 0.0;
#pragma unroll
                for (int w = 0; w < 8; w++) {
                    ds += (double)fs[w];
                    ds2 += (double)fs2[w];
                }
                double n = (double)(CDIM * NPIX);
                double mu = ds / n;
                double var = ds2 / n - mu * mu;
                stats[batch] = (float)mu;
                stats[8 + batch] = (float)(1.0 / sqrt(var + 1e-5));
                g_cnt[batch] = 0;                 // self-reset for graph replay
            }
        }
    }
}

// ---------------- depthwise 3x3, relu, split-emit ---------------------------------
__global__ void k_dwconv_split(const float* __restrict__ in, const float* __restrict__ wt,
                               const float* __restrict__ bs,
                               uint32_t* __restrict__ Xhi, uint32_t* __restrict__ Xlo) {
    int gid = blockIdx.x * 256 + threadIdx.x;
    if (gid >= TEN / 8) return;
    int p4 = gid & 1023;
    int c2 = (gid >> 10) & 63;
    int b = gid >> 16;
    int h = p4 >> 4, w4 = (p4 & 15) * 4;

    float acc[2][4];
#pragma unroll
    for (int cc = 0; cc < 2; cc++) {
        int c = 2 * c2 + cc;
        const float* ip = in + ((size_t)b * CDIM + c) * NPIX;
        const float* wc = wt + c * 9;
        float a0 = bs[c], a1 = a0, a2 = a0, a3 = a0;
#pragma unroll
        for (int ky = 0; ky < 3; ky++) {
            int hh = h + ky - 1;
            if ((unsigned)hh < 64u) {
                const float* rp = ip + hh * 64;
                float4 cv = *(const float4*)(rp + w4);
                float lv = (w4 > 0) ? rp[w4 - 1] : 0.f;
                float rv = (w4 + 4 < 64) ? rp[w4 + 4] : 0.f;
                float w0 = wc[ky * 3 + 0], w1 = wc[ky * 3 + 1], w2 = wc[ky * 3 + 2];
                a0 += w0 * lv   + w1 * cv.x + w2 * cv.y;
                a1 += w0 * cv.x + w1 * cv.y + w2 * cv.z;
                a2 += w0 * cv.y + w1 * cv.z + w2 * cv.w;
                a3 += w0 * cv.z + w1 * cv.w + w2 * rv;
            }
        }
        acc[cc][0] = fmaxf(a0, 0.f); acc[cc][1] = fmaxf(a1, 0.f);
        acc[cc][2] = fmaxf(a2, 0.f); acc[cc][3] = fmaxf(a3, 0.f);
    }
    uint4 h4, l4;
    pack2_hi_lo(acc[0][0], acc[1][0], h4.x, l4.x);
    pack2_hi_lo(acc[0][1], acc[1][1], h4.y, l4.y);
    pack2_hi_lo(acc[0][2], acc[1][2], h4.z, l4.z);
    pack2_hi_lo(acc[0][3], acc[1][3], h4.w, l4.w);
    size_t oi = ((size_t)b * 64 + c2) * NPIX + h * 64 + w4;
    *(uint4*)(Xhi + oi) = h4;
    *(uint4*)(Xlo + oi) = l4;
}

// ---------------- tensor-core conv1x1 GEMM (bf16x3, cp.async 3-stage) --------------
// FLAGS: bit2 RELU, bit3 ADD_RES, bit4 EMIT_SPLIT, bit5 IN_MULF, bit6 DUAL
template <int FLAGS>
__global__ void __launch_bounds__(256, 2)
k_gemm_tc(const uint32_t* __restrict__ Whig0, const uint32_t* __restrict__ Wlog0,
          const float* __restrict__ bias0,
          const uint32_t* __restrict__ Xhig, const uint32_t* __restrict__ Xlog,
          float* __restrict__ Y0, int O, int C,
          const float* __restrict__ resT,
          uint32_t* __restrict__ Uhi, uint32_t* __restrict__ Ulo,
          const float* __restrict__ Af, const float* __restrict__ Mf,
          const float* __restrict__ bias1, float* __restrict__ Y1) {
    constexpr bool ADDR = (FLAGS & 8) != 0;
    constexpr bool EMIT = (FLAGS & 16) != 0;
    constexpr bool MULF = (FLAGS & 32) != 0;
    constexpr bool DUAL = (FLAGS & 64) != 0;

    extern __shared__ uint32_t smg[];

    int tid = threadIdx.x;
    int lane = tid & 31, wid = tid >> 5;
    int warpM = wid >> 2, warpN = wid & 3;
    int g = lane >> 2, t = lane & 3;

    const uint32_t* Whig = Whig0;
    const uint32_t* Wlog = Wlog0;
    const float* bias = bias0;
    float* Y = Y0;
    bool relu_rt = (FLAGS & 4) != 0;
    int o0;
    if (DUAL) {
        if (blockIdx.y >= 2) {
            Whig += 8192; Wlog += 8192;
            bias = bias1; Y = Y1;
            relu_rt = false;
        }
        o0 = (blockIdx.y & 1) * 64;
    } else {
        o0 = blockIdx.y * 64;
    }
    int p0 = blockIdx.x * 128;
    int b = blockIdx.z;
    int c2n = C >> 1;
    int n_iter = c2n >> 4;

    const uint32_t* Xhb = Xhig ? (Xhig + (size_t)b * c2n * NPIX + p0) : nullptr;
    const uint32_t* Xlb = Xlog ? (Xlog + (size_t)b * c2n * NPIX + p0) : nullptr;

    float acc[2][4][4];
#pragma unroll
    for (int i = 0; i < 2; i++)
#pragma unroll
        for (int j = 0; j < 4; j++)
#pragma unroll
            for (int k = 0; k < 4; k++) acc[i][j][k] = 0.f;

    int wk = tid >> 4, wo = (tid & 15) * 4;
    int xk = tid >> 4, xn = (tid & 15) * 8;

    auto load_async = [&](int st, int kb2) {
        uint32_t* base = smg + st * GEMM_STAGE_U32;
        cp16(base + wk * 72 + wo,        Whig + (size_t)(kb2 + wk) * O + o0 + wo);
        cp16(base + 1152 + wk * 72 + wo, Wlog + (size_t)(kb2 + wk) * O + o0 + wo);
        const uint32_t* sh_ = Xhb + (size_t)(kb2 + xk) * NPIX + xn;
        const uint32_t* sl_ = Xlb + (size_t)(kb2 + xk) * NPIX + xn;
        cp16(base + 2304 + xk * 136 + xn,     sh_);
        cp16(base + 2304 + xk * 136 + xn + 4, sh_ + 4);
        cp16(base + 4480 + xk * 136 + xn,     sl_);
        cp16(base + 4480 + xk * 136 + xn + 4, sl_ + 4);
        asm volatile("cp.async.commit_group;");
    };

    auto load_mulf = [&](int kb2) {
        uint32_t* base = smg;
        *(uint4*)(base + wk * 72 + wo)        = *(const uint4*)(Whig + (size_t)(kb2 + wk) * O + o0 + wo);
        *(uint4*)(base + 1152 + wk * 72 + wo) = *(const uint4*)(Wlog + (size_t)(kb2 + wk) * O + o0 + wo);
        int c0 = (kb2 + xk) * 2;
        const float* a0 = Af + ((size_t)b * C + c0) * NPIX + p0 + xn;
        const float* a1 = a0 + NPIX;
        const float* m0 = Mf + ((size_t)b * C + c0) * NPIX + p0 + xn;
        const float* m1 = m0 + NPIX;
        float4 x0 = *(const float4*)(a0);
        float4 x1 = *(const float4*)(a0 + 4);
        float4 y0 = *(const float4*)(a1);
        float4 y1 = *(const float4*)(a1 + 4);
        float4 u0 = *(const float4*)(m0);
        float4 u1 = *(const float4*)(m0 + 4);
        float4 v0 = *(const float4*)(m1);
        float4 v1 = *(const float4*)(m1 + 4);
        float ra[8] = {x0.x * u0.x, x0.y * u0.y, x0.z * u0.z, x0.w * u0.w,
                       x1.x * u1.x, x1.y * u1.y, x1.z * u1.z, x1.w * u1.w};
        float rb[8] = {y0.x * v0.x, y0.y * v0.y, y0.z * v0.z, y0.w * v0.w,
                       y1.x * v1.x, y1.y * v1.y, y1.z * v1.z, y1.w * v1.w};
#pragma unroll
        for (int j = 0; j < 8; j++) {
            uint32_t hi, lo;
            pack2_hi_lo(ra[j], rb[j], hi, lo);
            base[2304 + xk * 136 + xn + j] = hi;
            base[4480 + xk * 136 + xn + j] = lo;
        }
    };

    auto compute = [&](int st) {
        uint32_t* Wh = smg + st * GEMM_STAGE_U32;
        uint32_t* Wl = Wh + 1152;
        uint32_t* Xh = Wh + 2304;
        uint32_t* Xl = Wh + 4480;
#pragma unroll
        for (int ks2 = 0; ks2 < 16; ks2 += 8) {
            uint32_t ah[2][4], al[2][4];
#pragma unroll
            for (int mt = 0; mt < 2; mt++) {
                int m0 = warpM * 32 + mt * 16;
                ah[mt][0] = Wh[(ks2 + t) * 72 + m0 + g];
                ah[mt][1] = Wh[(ks2 + t) * 72 + m0 + g + 8];
                ah[mt][2] = Wh[(ks2 + t + 4) * 72 + m0 + g];
                ah[mt][3] = Wh[(ks2 + t + 4) * 72 + m0 + g + 8];
                al[mt][0] = Wl[(ks2 + t) * 72 + m0 + g];
                al[mt][1] = Wl[(ks2 + t) * 72 + m0 + g + 8];
                al[mt][2] = Wl[(ks2 + t + 4) * 72 + m0 + g];
                al[mt][3] = Wl[(ks2 + t + 4) * 72 + m0 + g + 8];
            }
            uint32_t bh[4][2], bl[4][2];
#pragma unroll
            for (int nt = 0; nt < 4; nt++) {
                int n0 = warpN * 32 + nt * 8 + g;
                bh[nt][0] = Xh[(ks2 + t) * 136 + n0];
                bh[nt][1] = Xh[(ks2 + t + 4) * 136 + n0];
                bl[nt][0] = Xl[(ks2 + t) * 136 + n0];
                bl[nt][1] = Xl[(ks2 + t + 4) * 136 + n0];
            }
#pragma unroll
            for (int mt = 0; mt < 2; mt++)
#pragma unroll
                for (int nt = 0; nt < 4; nt++) {
                    mma_bf16(acc[mt][nt], ah[mt], bh[nt]);
                    mma_bf16(acc[mt][nt], ah[mt], bl[nt]);
                    mma_bf16(acc[mt][nt], al[mt], bh[nt]);
                }
        }
    };

    if constexpr (MULF) {
        for (int it = 0; it < n_iter; it++) {
            load_mulf(it * 16);
            __syncthreads();
            compute(0);
            __syncthreads();
        }
    } else {
        load_async(0, 0);
        if (n_iter > 1) load_async(1, 16);
        for (int it = 0; it < n_iter; it++) {
            if (it + 2 < n_iter) {
                load_async((it + 2) % 3, (it + 2) * 16);
                asm volatile("cp.async.wait_group 2;");
            } else if (it + 1 < n_iter) {
                asm volatile("cp.async.wait_group 1;");
            } else {
                asm volatile("cp.async.wait_group 0;");
            }
            __syncthreads();
            compute(it % 3);
            __syncthreads();
        }
    }

#pragma unroll
    for (int mt = 0; mt < 2; mt++) {
        int r0 = o0 + warpM * 32 + mt * 16 + g;
        int r1 = r0 + 8;
        float bi0 = bias[r0], bi1 = bias[r1];
#pragma unroll
        for (int nt = 0; nt < 4; nt++) {
            int cc = p0 + warpN * 32 + nt * 8 + t * 2;
            float v00 = acc[mt][nt][0] + bi0;
            float v01 = acc[mt][nt][1] + bi0;
            float v10 = acc[mt][nt][2] + bi1;
            float v11 = acc[mt][nt][3] + bi1;
            if (relu_rt) {
                v00 = fmaxf(v00, 0.f); v01 = fmaxf(v01, 0.f);
                v10 = fmaxf(v10, 0.f); v11 = fmaxf(v11, 0.f);
            }
            if (EMIT) {
                float p00 = __shfl_xor_sync(0xffffffffu, v00, 4);
                float p01 = __shfl_xor_sync(0xffffffffu, v01, 4);
                float p10 = __shfl_xor_sync(0xffffffffu, v10, 4);
                float p11 = __shfl_xor_sync(0xffffffffu, v11, 4);
                if ((g & 1) == 0) {
                    uint32_t h0, l0, h1, l1;
                    pack2_hi_lo(v00, p00, h0, l0);
                    pack2_hi_lo(v01, p01, h1, l1);
                    size_t oi0 = ((size_t)b * (O >> 1) + (r0 >> 1)) * NPIX + cc;
                    *(uint2*)(Uhi + oi0) = make_uint2(h0, h1);
                    *(uint2*)(Ulo + oi0) = make_uint2(l0, l1);
                    pack2_hi_lo(v10, p10, h0, l0);
                    pack2_hi_lo(v11, p11, h1, l1);
                    size_t oi1 = ((size_t)b * (O >> 1) + (r1 >> 1)) * NPIX + cc;
                    *(uint2*)(Uhi + oi1) = make_uint2(h0, h1);
                    *(uint2*)(Ulo + oi1) = make_uint2(l0, l1);
                }
            } else {
                size_t i0 = ((size_t)b * O + r0) * NPIX + cc;
                size_t i1 = ((size_t)b * O + r1) * NPIX + cc;
                if (ADDR) {
                    float2 q0 = *(const float2*)(resT + i0);
                    float2 q1 = *(const float2*)(resT + i1);
                    v00 += q0.x; v01 += q0.y; v10 += q1.x; v11 += q1.y;
                }
                *(float2*)(Y + i0) = make_float2(v00, v01);
                *(float2*)(Y + i1) = make_float2(v10, v11);
            }
        }
    }
}

// ---------------- MMA windowed attention (both variants, one launch) ---------------
__global__ void __launch_bounds__(128)
k_attn_mma(const float* __restrict__ qkv, float* __restrict__ out) {
    extern __shared__ char smem_raw[];
    uint32_t* Khi = (uint32_t*)smem_raw;
    uint32_t* Klo = Khi + 2048;
    uint32_t* Vhi = Klo + 2048;
    uint32_t* Vlo = Vhi + 2048;
    uint32_t* Qhi = Vlo + 2048;
    uint32_t* Qlo = Qhi + 2048;
    float* Osm = (float*)smem_raw;

    int tid = threadIdx.x;
    int lane = tid & 31, wrp = tid >> 5;
    int g = lane >> 2, t = lane & 3;
    int bx0 = blockIdx.x;
    int variant = bx0 >> 10;
    int bx = bx0 & 1023;
    int head = bx & 7;
    int widx = (bx >> 3) & 15;
    int b = bx >> 7;
    int qoff = variant ? 3 : 0;
    int koff = qoff + 1;

    size_t cbase = ((size_t)(b * 640 + head * 80)) * NPIX;

#pragma unroll
    for (int i = 0; i < 4; i++) {
        int gidx = tid + i * 128;
        int dp = gidx >> 6, grp = gidx & 63;
        int pix0 = (variant == 0) ? grp * 64 + widx * 4
                                  : (widx * 4 + (grp >> 4)) * 64 + (grp & 15) * 4;
        int l0 = grp * 4;
        const float* q0p = qkv + cbase + (size_t)(5 * (2 * dp) + qoff) * NPIX + pix0;
        const float* q1p = qkv + cbase + (size_t)(5 * (2 * dp + 1) + qoff) * NPIX + pix0;
        float4 qa = *(const float4*)q0p;
        float4 qb = *(const float4*)q1p;
        uint32_t hi, lo;
        pack2_hi_lo(qa.x, qb.x, hi, lo); Qhi[(l0 + 0) * 8 + dp] = hi; Qlo[(l0 + 0) * 8 + dp] = lo;
        pack2_hi_lo(qa.y, qb.y, hi, lo); Qhi[(l0 + 1) * 8 + dp] = hi; Qlo[(l0 + 1) * 8 + dp] = lo;
        pack2_hi_lo(qa.z, qb.z, hi, lo); Qhi[(l0 + 2) * 8 + dp] = hi; Qlo[(l0 + 2) * 8 + dp] = lo;
        pack2_hi_lo(qa.w, qb.w, hi, lo); Qhi[(l0 + 3) * 8 + dp] = hi; Qlo[(l0 + 3) * 8 + dp] = lo;
        const float* k0p = qkv + cbase + (size_t)(5 * (2 * dp) + koff) * NPIX + pix0;
        const float* k1p = qkv + cbase + (size_t)(5 * (2 * dp + 1) + koff) * NPIX + pix0;
        float4 ka = *(const float4*)k0p;
        float4 kb = *(const float4*)k1p;
        pack2_hi_lo(ka.x, kb.x, hi, lo); Khi[(l0 + 0) * 8 + dp] = hi; Klo[(l0 + 0) * 8 + dp] = lo;
        pack2_hi_lo(ka.y, kb.y, hi, lo); Khi[(l0 + 1) * 8 + dp] = hi; Klo[(l0 + 1) * 8 + dp] = lo;
        pack2_hi_lo(ka.z, kb.z, hi, lo); Khi[(l0 + 2) * 8 + dp] = hi; Klo[(l0 + 2) * 8 + dp] = lo;
        pack2_hi_lo(ka.w, kb.w, hi, lo); Khi[(l0 + 3) * 8 + dp] = hi; Klo[(l0 + 3) * 8 + dp] = lo;
    }
#pragma unroll
    for (int i = 0; i < 8; i++) {
        int gidx = tid + i * 128;
        int d = gidx >> 6, grp = gidx & 63;
        int pix0 = (variant == 0) ? grp * 64 + widx * 4
                                  : (widx * 4 + (grp >> 4)) * 64 + (grp & 15) * 4;
        const float* vp = qkv + cbase + (size_t)(5 * d + 2) * NPIX + pix0;
        float4 v = *(const float4*)vp;
        uint32_t hi, lo;
        pack2_hi_lo(v.x, v.y, hi, lo); Vhi[d * 128 + grp * 2] = hi;     Vlo[d * 128 + grp * 2] = lo;
        pack2_hi_lo(v.z, v.w, hi, lo); Vhi[d * 128 + grp * 2 + 1] = hi; Vlo[d * 128 + grp * 2 + 1] = lo;
    }
    __syncthreads();

    uint32_t qah[4][4], qal[4][4];
#pragma unroll
    for (int mt = 0; mt < 4; mt++) {
        int r = wrp * 64 + mt * 16 + g;
        qah[mt][0] = Qhi[r * 8 + t];       qah[mt][1] = Qhi[(r + 8) * 8 + t];
        qah[mt][2] = Qhi[r * 8 + t + 4];   qah[mt][3] = Qhi[(r + 8) * 8 + t + 4];
        qal[mt][0] = Qlo[r * 8 + t];       qal[mt][1] = Qlo[(r + 8) * 8 + t];
        qal[mt][2] = Qlo[r * 8 + t + 4];   qal[mt][3] = Qlo[(r + 8) * 8 + t + 4];
    }

    float Oa[4][2][4];
    float mrun[4][2], lrun[4][2];
#pragma unroll
    for (int mt = 0; mt < 4; mt++) {
        mrun[mt][0] = -1e30f; mrun[mt][1] = -1e30f;
        lrun[mt][0] = 0.f;    lrun[mt][1] = 0.f;
#pragma unroll
        for (int nt = 0; nt < 2; nt++)
#pragma unroll
            for (int j = 0; j < 4; j++) Oa[mt][nt][j] = 0.f;
    }

    for (int kt = 0; kt < 16; kt++) {
        int key0 = kt * 16;
        uint32_t kbh[2][2], kbl[2][2];
        {
            int kr0 = (key0 + g) * 8, kr1 = (key0 + 8 + g) * 8;
            kbh[0][0] = Khi[kr0 + t]; kbh[0][1] = Khi[kr0 + t + 4];
            kbh[1][0] = Khi[kr1 + t]; kbh[1][1] = Khi[kr1 + t + 4];
            kbl[0][0] = Klo[kr0 + t]; kbl[0][1] = Klo[kr0 + t + 4];
            kbl[1][0] = Klo[kr1 + t]; kbl[1][1] = Klo[kr1 + t + 4];
        }
        uint32_t vbh[2][2], vbl[2][2];
        {
            int kp = (key0 >> 1) + t;
            vbh[0][0] = Vhi[g * 128 + kp];        vbh[0][1] = Vhi[g * 128 + kp + 4];
            vbh[1][0] = Vhi[(g + 8) * 128 + kp];  vbh[1][1] = Vhi[(g + 8) * 128 + kp + 4];
            vbl[0][0] = Vlo[g * 128 + kp];        vbl[0][1] = Vlo[g * 128 + kp + 4];
            vbl[1][0] = Vlo[(g + 8) * 128 + kp];  vbl[1][1] = Vlo[(g + 8) * 128 + kp + 4];
        }
#pragma unroll
        for (int mt = 0; mt < 4; mt++) {
            float S[2][4];
#pragma unroll
            for (int nt = 0; nt < 2; nt++)
#pragma unroll
                for (int j = 0; j < 4; j++) S[nt][j] = 0.f;
            mma_bf16(S[0], qah[mt], kbh[0]);
            mma_bf16(S[0], qah[mt], kbl[0]);
            mma_bf16(S[0], qal[mt], kbh[0]);
            mma_bf16(S[1], qah[mt], kbh[1]);
            mma_bf16(S[1], qah[mt], kbl[1]);
            mma_bf16(S[1], qal[mt], kbh[1]);

            float mx0 = fmaxf(fmaxf(S[0][0], S[0][1]), fmaxf(S[1][0], S[1][1]));
            float mx1 = fmaxf(fmaxf(S[0][2], S[0][3]), fmaxf(S[1][2], S[1][3]));
            mx0 = fmaxf(mx0, __shfl_xor_sync(0xffffffffu, mx0, 1));
            mx0 = fmaxf(mx0, __shfl_xor_sync(0xffffffffu, mx0, 2));
            mx1 = fmaxf(mx1, __shfl_xor_sync(0xffffffffu, mx1, 1));
            mx1 = fmaxf(mx1, __shfl_xor_sync(0xffffffffu, mx1, 2));
            float mn0 = fmaxf(mrun[mt][0], mx0);
            float mn1 = fmaxf(mrun[mt][1], mx1);
            float f0 = __expf(mrun[mt][0] - mn0);
            float f1 = __expf(mrun[mt][1] - mn1);
            mrun[mt][0] = mn0; mrun[mt][1] = mn1;

            float p[2][4];
            p[0][0] = __expf(S[0][0] - mn0); p[0][1] = __expf(S[0][1] - mn0);
            p[0][2] = __expf(S[0][2] - mn1); p[0][3] = __expf(S[0][3] - mn1);
            p[1][0] = __expf(S[1][0] - mn0); p[1][1] = __expf(S[1][1] - mn0);
            p[1][2] = __expf(S[1][2] - mn1); p[1][3] = __expf(S[1][3] - mn1);

            float rs0 = p[0][0] + p[0][1] + p[1][0] + p[1][1];
            float rs1 = p[0][2] + p[0][3] + p[1][2] + p[1][3];
            rs0 += __shfl_xor_sync(0xffffffffu, rs0, 1);
            rs0 += __shfl_xor_sync(0xffffffffu, rs0, 2);
            rs1 += __shfl_xor_sync(0xffffffffu, rs1, 1);
            rs1 += __shfl_xor_sync(0xffffffffu, rs1, 2);
            lrun[mt][0] = lrun[mt][0] * f0 + rs0;
            lrun[mt][1] = lrun[mt][1] * f1 + rs1;

#pragma unroll
            for (int nt = 0; nt < 2; nt++) {
                Oa[mt][nt][0] *= f0; Oa[mt][nt][1] *= f0;
                Oa[mt][nt][2] *= f1; Oa[mt][nt][3] *= f1;
            }

            uint32_t pah[4], pal[4];
            pack2_hi_lo(p[0][0], p[0][1], pah[0], pal[0]);
            pack2_hi_lo(p[0][2], p[0][3], pah[1], pal[1]);
            pack2_hi_lo(p[1][0], p[1][1], pah[2], pal[2]);
            pack2_hi_lo(p[1][2], p[1][3], pah[3], pal[3]);

            mma_bf16(Oa[mt][0], pah, vbh[0]);
            mma_bf16(Oa[mt][0], pah, vbl[0]);
            mma_bf16(Oa[mt][0], pal, vbh[0]);
            mma_bf16(Oa[mt][1], pah, vbh[1]);
            mma_bf16(Oa[mt][1], pah, vbl[1]);
            mma_bf16(Oa[mt][1], pal, vbh[1]);
        }
    }

    __syncthreads();

#pragma unroll
    for (int mt = 0; mt < 4; mt++) {
        int r = wrp * 64 + mt * 16 + g;
        float i0 = 1.f / lrun[mt][0];
        float i1 = 1.f / lrun[mt][1];
        Osm[r * 20 + 2 * t]           = Oa[mt][0][0] * i0;
        Osm[r * 20 + 2 * t + 1]       = Oa[mt][0][1] * i0;
        Osm[(r + 8) * 20 + 2 * t]     = Oa[mt][0][2] * i1;
        Osm[(r + 8) * 20 + 2 * t + 1] = Oa[mt][0][3] * i1;
        Osm[r * 20 + 8 + 2 * t]           = Oa[mt][1][0] * i0;
        Osm[r * 20 + 8 + 2 * t + 1]       = Oa[mt][1][1] * i0;
        Osm[(r + 8) * 20 + 8 + 2 * t]     = Oa[mt][1][2] * i1;
        Osm[(r + 8) * 20 + 8 + 2 * t + 1] = Oa[mt][1][3] * i1;
    }
    __syncthreads();

#pragma unroll
    for (int i = 0; i < 8; i++) {
        int gidx = tid + i * 128;
        int d = gidx >> 6, grp = gidx & 63;
        int pix0 = (variant == 0) ? grp * 64 + widx * 4
                                  : (widx * 4 + (grp >> 4)) * 64 + (grp & 15) * 4;
        int l0 = grp * 4;
        float* op = out + ((size_t)(b * 128 + head * 16 + d)) * NPIX + pix0;
        float4 cur = *(float4*)op;
        cur.x += Osm[(l0 + 0) * 20 + d];
        cur.y += Osm[(l0 + 1) * 20 + d];
        cur.z += Osm[(l0 + 2) * 20 + d];
        cur.w += Osm[(l0 + 3) * 20 + d];
        *(float4*)op = cur;
    }
}

// ---------------- orchestration ------------------------------------------------
extern "C" void kernel_launch(void* const* d_in, const int* in_sizes, int n_in,
                              void* d_out, int out_size) {
    (void)in_sizes; (void)n_in; (void)out_size;
    const float* x      = (const float*)d_in[0];
    const float* eca_w  = (const float*)d_in[1];
    const float* esa_a  = (const float*)d_in[2];
    const float* cpe1_w = (const float*)d_in[3];
    const float* cpe1_b = (const float*)d_in[4];
    const float* g1     = (const float*)d_in[5];
    const float* b1     = (const float*)d_in[6];
    const float* actp_w = (const float*)d_in[7];
    const float* actp_b = (const float*)d_in[8];
    const float* inp_w  = (const float*)d_in[9];
    const float* inp_b  = (const float*)d_in[10];
    const float* dwc_w  = (const float*)d_in[11];
    const float* dwc_b  = (const float*)d_in[12];
    const float* qkv_w  = (const float*)d_in[13];
    const float* qkv_b  = (const float*)d_in[14];
    const float* eaax_w = (const float*)d_in[15];
    const float* eaax_b = (const float*)d_in[16];
    const float* eaay_w = (const float*)d_in[17];
    const float* eaay_b = (const float*)d_in[18];
    const float* outp_w = (const float*)d_in[19];
    const float* outp_b = (const float*)d_in[20];
    const float* cpe2_w = (const float*)d_in[21];
    const float* cpe2_b = (const float*)d_in[22];
    const float* g2     = (const float*)d_in[23];
    const float* b2     = (const float*)d_in[24];
    const float* mlp1_w = (const float*)d_in[25];
    const float* mlp1_b = (const float*)d_in[26];
    const float* mlp2_w = (const float*)d_in[27];
    const float* mlp2_b = (const float*)d_in[28];
    float* out = (float*)d_out;

    float *bufA, *bufB, *bufC, *bufD, *qkv, *m, *st1, *st2, *cw, *cb, *gnp;
    uint32_t *xhi, *xlo, *yhi, *ylo, *whi, *wlo;
    cudaGetSymbolAddress((void**)&bufA, g_bufA);
    cudaGetSymbolAddress((void**)&bufB, g_bufB);
    cudaGetSymbolAddress((void**)&bufC, g_bufC);
    cudaGetSymbolAddress((void**)&bufD, g_bufD);
    cudaGetSymbolAddress((void**)&qkv,  g_qkv);
    cudaGetSymbolAddress((void**)&m,    g_m);
    cudaGetSymbolAddress((void**)&gnp,  g_gnpart);
    cudaGetSymbolAddress((void**)&st1,  g_stats1);
    cudaGetSymbolAddress((void**)&st2,  g_stats2);
    cudaGetSymbolAddress((void**)&cw,   g_cpe_w);
    cudaGetSymbolAddress((void**)&cb,   g_cpe_b);
    cudaGetSymbolAddress((void**)&xhi,  g_xhi);
    cudaGetSymbolAddress((void**)&xlo,  g_xlo);
    cudaGetSymbolAddress((void**)&yhi,  g_yhi);
    cudaGetSymbolAddress((void**)&ylo,  g_ylo);
    cudaGetSymbolAddress((void**)&whi,  g_whi);
    cudaGetSymbolAddress((void**)&wlo,  g_wlo);

    cudaFuncSetAttribute(k_attn_mma, cudaFuncAttributeMaxDynamicSharedMemorySize, ATTN_SMEM);
    cudaFuncSetAttribute(k_gemm_tc<0>,      cudaFuncAttributeMaxDynamicSharedMemorySize, GEMM_SMEM);
    cudaFuncSetAttribute(k_gemm_tc<8>,      cudaFuncAttributeMaxDynamicSharedMemorySize, GEMM_SMEM);
    cudaFuncSetAttribute(k_gemm_tc<4 | 16>, cudaFuncAttributeMaxDynamicSharedMemorySize, GEMM_SMEM);
    cudaFuncSetAttribute(k_gemm_tc<8 | 32>, cudaFuncAttributeMaxDynamicSharedMemorySize, GEMM_SMEM);
    cudaFuncSetAttribute(k_gemm_tc<4 | 64>, cudaFuncAttributeMaxDynamicSharedMemorySize, GEMM_SMEM);

    const int DW_GRID = (TEN / 4) / 256;
    const int XP128 = (BATCH * 64 * 1024) / 256;
    dim3 ggDual(32, 4, 8), gg128(32, 2, 8), gg640(32, 10, 8), gg512(32, 8, 8);

    // 0) merged prep
    k_prep<<<1537, 256>>>(actp_w, inp_w, qkv_w, outp_w, mlp1_w, mlp2_w,
                          x, m, eaax_w, eaax_b, eaay_w, eaay_b);

    // 1) eca+esa
    k_ecaesa<<<512, 256>>>(x, m, eca_w, esa_a, bufA);

    // 2) x1 = y1 + dwconv(cpe1) -> bufB = shortcut; GN1 stats finalized in-kernel
    k_dwconv4<1><<<DW_GRID, 256>>>(bufA, cpe1_w, cpe1_b, bufB, 1, 1, 0, CDIM * NPIX, gnp, st1);

    // 3) preconvert gn(x1)
    k_xprep<1><<<XP128, 256>>>(bufB, nullptr, xhi, xlo, st1, g1, b1);

    // 4) DUAL GEMM: act_res / u
    k_gemm_tc<4 | 64><<<ggDual, 256, GEMM_SMEM>>>(whi + WOFF_ACTP, wlo + WOFF_ACTP, actp_b,
                                                  xhi, xlo, bufC, 128, 128,
                                                  nullptr, nullptr, nullptr, nullptr, nullptr,
                                                  inp_b, bufA);

    // 5) t = relu(dwconv(u)) -> split into xhi/xlo
    k_dwconv_split<<<(TEN / 8) / 256, 256>>>(bufA, dwc_w, dwc_b, xhi, xlo);

    // 6) qkv
    k_gemm_tc<0><<<gg640, 256, GEMM_SMEM>>>(whi + WOFF_QKV, wlo + WOFF_QKV, qkv_b, xhi, xlo, qkv, 640, 128, nullptr, nullptr, nullptr, nullptr, nullptr, nullptr, nullptr);

    // 7) cpe dwconv + both attentions
    k_dwconv4<0><<<DW_GRID, 256>>>(qkv, cw, cb, bufA, 0, 5, 2, 640 * NPIX, nullptr, nullptr);
    k_attn_mma<<<2048, 128, ATTN_SMEM>>>(qkv, bufA);

    // 8) out1 = outp(a * act_res) + shortcut
    k_gemm_tc<8 | 32><<<gg128, 256, GEMM_SMEM>>>(whi + WOFF_OUTP, wlo + WOFF_OUTP, outp_b, nullptr, nullptr, bufD, 128, 128, bufB, nullptr, nullptr, bufA, bufC, nullptr, nullptr);

    // 9) out2 = out1 + dwconv(cpe2); GN2 stats finalized in-kernel
    k_dwconv4<1><<<DW_GRID, 256>>>(bufD, cpe2_w, cpe2_b, bufA, 1, 1, 0, CDIM * NPIX, gnp, st2);

    // 10) MLP + residual
    k_xprep<1><<<XP128, 256>>>(bufA, nullptr, xhi, xlo, st2, g2, b2);
    k_gemm_tc<4 | 16><<<gg512, 256, GEMM_SMEM>>>(whi + WOFF_MLP1, wlo + WOFF_MLP1, mlp1_b, xhi, xlo, nullptr, 512, 128, nullptr, yhi, ylo, nullptr, nullptr, nullptr, nullptr);
    k_gemm_tc<8><<<gg128, 256, GEMM_SMEM>>>(whi + WOFF_MLP2, wlo + WOFF_MLP2, mlp2_b, yhi, ylo, out, 128, 512, bufA, nullptr, nullptr, nullptr, nullptr, nullptr, nullptr);
}

// round 17
// speedup vs baseline: 1.0605x; 1.0605x over previous
#include <cuda_runtime.h>
#include <cuda_bf16.h>
#include <math.h>
#include <stdint.h>

#define BATCH 8
#define CDIM  128
#define NPIX  4096
#define TEN   (BATCH*CDIM*NPIX)

// ---------------- scratch ----------------------------------------------------
__device__ float g_bufA[TEN];
__device__ float g_bufB[TEN];
__device__ float g_bufC[TEN];
__device__ float g_bufD[TEN];
__device__ float g_qkv[BATCH * 640 * NPIX];
__device__ uint32_t g_xhi[BATCH * 64 * NPIX];
__device__ uint32_t g_xlo[BATCH * 64 * NPIX];
__device__ uint32_t g_yhi[BATCH * 256 * NPIX];
__device__ uint32_t g_ylo[BATCH * 256 * NPIX];
__device__ uint32_t g_whi[131072];
__device__ uint32_t g_wlo[131072];
__device__ float g_m[BATCH * CDIM];
__device__ float g_gnpart[65536];
__device__ float g_stats1[16];
__device__ float g_stats2[16];
__device__ float g_cpe_w[CDIM * 9];
__device__ float g_cpe_b[CDIM];

#define WOFF_ACTP 0
#define WOFF_INP  8192
#define WOFF_QKV  16384
#define WOFF_OUTP 57344
#define WOFF_MLP1 65536
#define WOFF_MLP2 98304

#define ATTN_SMEM 49152
#define GEMM_STAGE_U32 6656
#define GEMM_SMEM (GEMM_STAGE_U32 * 3 * 4)

// ---------------- helpers ----------------------------------------------------
__device__ __forceinline__ void pack2_hi_lo(float a, float b,
                                            uint32_t& hi, uint32_t& lo) {
    __nv_bfloat16 ha = __float2bfloat16_rn(a);
    __nv_bfloat16 hb = __float2bfloat16_rn(b);
    float ra = a - __bfloat162float(ha);
    float rb = b - __bfloat162float(hb);
    __nv_bfloat162 hv = __nv_bfloat162(ha, hb);
    __nv_bfloat162 lv = __floats2bfloat162_rn(ra, rb);
    hi = *(uint32_t*)&hv;
    lo = *(uint32_t*)&lv;
}

__device__ __forceinline__ uint32_t pack2_hi(float a, float b) {
    __nv_bfloat162 hv = __floats2bfloat162_rn(a, b);
    return *(uint32_t*)&hv;
}

__device__ __forceinline__ void mma_bf16(float* d, const uint32_t* a, const uint32_t* b) {
    asm volatile(
        "mma.sync.aligned.m16n8k16.row.col.f32.bf16.bf16.f32 "
        "{%0,%1,%2,%3}, {%4,%5,%6,%7}, {%8,%9}, {%0,%1,%2,%3};"
        : "+f"(d[0]), "+f"(d[1]), "+f"(d[2]), "+f"(d[3])
        : "r"(a[0]), "r"(a[1]), "r"(a[2]), "r"(a[3]), "r"(b[0]), "r"(b[1]));
}

__device__ __forceinline__ void cp16(uint32_t* smem_dst, const uint32_t* gsrc) {
    uint32_t s = (uint32_t)__cvta_generic_to_shared(smem_dst);
    asm volatile("cp.async.cg.shared.global [%0], [%1], 16;" :: "r"(s), "l"(gsrc));
}

// ---------------- merged prep: wprep (blk 0-511) + gap (512-1535) + combine (1536)
__global__ void k_prep(const float* __restrict__ actp, const float* __restrict__ inp,
                       const float* __restrict__ qkv,  const float* __restrict__ outp,
                       const float* __restrict__ mlp1, const float* __restrict__ mlp2,
                       const float* __restrict__ x, float* __restrict__ m,
                       const float* __restrict__ wx, const float* __restrict__ bx,
                       const float* __restrict__ wy, const float* __restrict__ by) {
    int blk = blockIdx.x;
    if (blk < 512) {
        int gid = blk * 256 + threadIdx.x;
        const float* W; int O, C, base;
        if (gid < 8192)       { W = actp; O = 128; C = 128; base = WOFF_ACTP; }
        else if (gid < 16384) { W = inp;  O = 128; C = 128; base = WOFF_INP;  }
        else if (gid < 57344) { W = qkv;  O = 640; C = 128; base = WOFF_QKV;  }
        else if (gid < 65536) { W = outp; O = 128; C = 128; base = WOFF_OUTP; }
        else if (gid < 98304) { W = mlp1; O = 512; C = 128; base = WOFF_MLP1; }
        else                  { W = mlp2; O = 128; C = 512; base = WOFF_MLP2; }
        int idx = gid - base;
        int kp = idx / O, o = idx - kp * O;
        float a = W[(size_t)o * C + 2 * kp];
        float b = W[(size_t)o * C + 2 * kp + 1];
        uint32_t hi, lo;
        pack2_hi_lo(a, b, hi, lo);
        g_whi[base + idx] = hi;
        g_wlo[base + idx] = lo;
    } else if (blk < 1536) {
        int bc = blk - 512;
        const float4* p = (const float4*)(x + (size_t)bc * NPIX);
        float s = 0.f;
        for (int i = threadIdx.x; i < NPIX / 4; i += 256) {
            float4 v = p[i];
            s += v.x + v.y + v.z + v.w;
        }
        __shared__ float sm[256];
        sm[threadIdx.x] = s;
        __syncthreads();
        for (int st = 128; st > 0; st >>= 1) {
            if (threadIdx.x < st) sm[threadIdx.x] += sm[threadIdx.x + st];
            __syncthreads();
        }
        if (threadIdx.x == 0) m[bc] = sm[0] * (1.f / NPIX);
    } else {
        for (int i = threadIdx.x; i < CDIM * 9; i += 256) g_cpe_w[i] = wx[i] + wy[i];
        if (threadIdx.x < CDIM) g_cpe_b[threadIdx.x] = bx[threadIdx.x] + by[threadIdx.x];
    }
}

// ---------------- X preconversion ----------------------------------------------
template <int FLAGS>
__global__ void k_xprep(const float* __restrict__ X, const float* __restrict__ mulT,
                        uint32_t* __restrict__ Xhi, uint32_t* __restrict__ Xlo,
                        const float* __restrict__ stats,
                        const float* __restrict__ gam, const float* __restrict__ bet) {
    constexpr bool GN  = (FLAGS & 1) != 0;
    constexpr bool MUL = (FLAGS & 2) != 0;
    const int C = 128, c2n = 64;
    int gid = blockIdx.x * 256 + threadIdx.x;
    if (gid >= BATCH * c2n * 1024) return;
    int b = gid / (c2n * 1024);
    int r = gid - b * c2n * 1024;
    int c2 = r >> 10;
    int p4 = (r & 1023) << 2;
    int c0 = 2 * c2;

    const float* s0 = X + ((size_t)b * C + c0) * NPIX + p4;
    float4 a = *(const float4*)(s0);
    float4 d = *(const float4*)(s0 + NPIX);
    if (MUL) {
        const float* m0 = mulT + ((size_t)b * C + c0) * NPIX + p4;
        float4 u = *(const float4*)(m0);
        float4 v = *(const float4*)(m0 + NPIX);
        a.x *= u.x; a.y *= u.y; a.z *= u.z; a.w *= u.w;
        d.x *= v.x; d.y *= v.y; d.z *= v.z; d.w *= v.w;
    }
    if (GN) {
        float mu = stats[b], rs = stats[8 + b];
        float sc0 = gam[c0] * rs,     of0 = bet[c0] - mu * sc0;
        float sc1 = gam[c0 + 1] * rs, of1 = bet[c0 + 1] - mu * sc1;
        a.x = a.x * sc0 + of0; a.y = a.y * sc0 + of0;
        a.z = a.z * sc0 + of0; a.w = a.w * sc0 + of0;
        d.x = d.x * sc1 + of1; d.y = d.y * sc1 + of1;
        d.z = d.z * sc1 + of1; d.w = d.w * sc1 + of1;
    }
    uint4 h4, l4;
    pack2_hi_lo(a.x, d.x, h4.x, l4.x);
    pack2_hi_lo(a.y, d.y, h4.y, l4.y);
    pack2_hi_lo(a.z, d.z, h4.z, l4.z);
    pack2_hi_lo(a.w, d.w, h4.w, l4.w);
    size_t oi = ((size_t)b * c2n + c2) * NPIX + p4;
    *(uint4*)(Xhi + oi) = h4;
    *(uint4*)(Xlo + oi) = l4;
}

// ---------------- fused gate + eca + esa -----------------------------------------
__global__ void __launch_bounds__(256)
k_ecaesa(const float* __restrict__ x, const float* __restrict__ m,
         const float* __restrict__ eca_w, const float* __restrict__ alphaP,
         float* __restrict__ y) {
    __shared__ float msm[128], gates[128];
    __shared__ float pmax[4][64], pmin[4][64], sas[64];
    int bp = blockIdx.x;
    int b = bp >> 6;
    int p0 = (bp & 63) * 64;
    int tid = threadIdx.x;
    int pix = tid & 63, grp = tid >> 6;

    if (tid < 128) msm[tid] = m[b * 128 + tid];
    __syncthreads();
    if (tid < 128) {
        float s = 0.f;
#pragma unroll
        for (int t2 = 0; t2 < 5; t2++) {
            int cc = tid + t2 - 2;
            if (cc >= 0 && cc < 128) s += eca_w[t2] * msm[cc];
        }
        gates[tid] = 1.f / (1.f + __expf(-s));
    }

    const float* xp = x + (size_t)b * CDIM * NPIX + p0 + pix;
    float xv[32];
    float vmax = -1e30f, vmin = 1e30f;
#pragma unroll
    for (int i = 0; i < 32; i++) {
        int c = grp * 32 + i;
        float v = xp[(size_t)c * NPIX];
        xv[i] = v;
        float d = v - msm[c];
        vmax = fmaxf(vmax, d);
        vmin = fminf(vmin, d);
    }
    pmax[grp][pix] = vmax;
    pmin[grp][pix] = vmin;
    __syncthreads();
    if (tid < 64) {
        float a = alphaP[0];
        float mx = fmaxf(fmaxf(pmax[0][tid], pmax[1][tid]), fmaxf(pmax[2][tid], pmax[3][tid]));
        float mn = fminf(fminf(pmin[0][tid], pmin[1][tid]), fminf(pmin[2][tid], pmin[3][tid]));
        sas[tid] = a / (1.f + __expf(-mx)) + (1.f - a) / (1.f + __expf(-mn));
    }
    __syncthreads();
    float* yp = y + (size_t)b * CDIM * NPIX + p0 + pix;
    float sa = sas[pix];
#pragma unroll
    for (int i = 0; i < 32; i++) {
        int c = grp * 32 + i;
        yp[(size_t)c * NPIX] = xv[i] * (gates[c] + sa);
    }
}

// ---------------- depthwise 3x3, 4 outputs/thread, templated GN partials ----------
template <int GNPART>
__global__ void k_dwconv4(const float* __restrict__ in, const float* __restrict__ wt,
                          const float* __restrict__ bs, float* __restrict__ out,
                          int mode, int cmul, int coff, int in_bstride,
                          float* __restrict__ part) {
    int gid = blockIdx.x * blockDim.x + threadIdx.x;
    int p4 = gid & 1023;
    int c = (gid >> 10) & 127;
    int b = gid >> 17;
    int h = p4 >> 4, w4 = (p4 & 15) * 4;
    const float* ip = in + (size_t)b * in_bstride + (size_t)(c * cmul + coff) * NPIX;
    const float* wc = wt + c * 9;

    float acc0 = bs[c], acc1 = acc0, acc2 = acc0, acc3 = acc0;
    float ctr[4];

#pragma unroll
    for (int ky = 0; ky < 3; ky++) {
        int hh = h + ky - 1;
        if ((unsigned)hh < 64u) {
            const float* rp = ip + hh * 64;
            float4 cv = *(const float4*)(rp + w4);
            float lv = (w4 > 0) ? rp[w4 - 1] : 0.f;
            float rv = (w4 + 4 < 64) ? rp[w4 + 4] : 0.f;
            float v0 = lv, v1 = cv.x, v2 = cv.y, v3 = cv.z, v4 = cv.w, v5 = rv;
            float w0 = wc[ky * 3 + 0], w1 = wc[ky * 3 + 1], w2 = wc[ky * 3 + 2];
            acc0 += w0 * v0 + w1 * v1 + w2 * v2;
            acc1 += w0 * v1 + w1 * v2 + w2 * v3;
            acc2 += w0 * v2 + w1 * v3 + w2 * v4;
            acc3 += w0 * v3 + w1 * v4 + w2 * v5;
            if (ky == 1) { ctr[0] = v1; ctr[1] = v2; ctr[2] = v3; ctr[3] = v4; }
        }
    }
    if (mode == 1) { acc0 += ctr[0]; acc1 += ctr[1]; acc2 += ctr[2]; acc3 += ctr[3]; }
    if (mode == 2) {
        acc0 = fmaxf(acc0, 0.f); acc1 = fmaxf(acc1, 0.f);
        acc2 = fmaxf(acc2, 0.f); acc3 = fmaxf(acc3, 0.f);
    }
    *(float4*)(out + (size_t)gid * 4) = make_float4(acc0, acc1, acc2, acc3);

    if (GNPART) {
        float s = acc0 + acc1 + acc2 + acc3;
        float s2 = acc0 * acc0 + acc1 * acc1 + acc2 * acc2 + acc3 * acc3;
#pragma unroll
        for (int off = 16; off > 0; off >>= 1) {
            s  += __shfl_down_sync(0xffffffffu, s,  off);
            s2 += __shfl_down_sync(0xffffffffu, s2, off);
        }
        if ((threadIdx.x & 31) == 0) {
            int slot = blockIdx.x * 8 + (threadIdx.x >> 5);
            part[slot * 2]     = s;
            part[slot * 2 + 1] = s2;
        }
    }
}

// ---------------- depthwise 3x3, relu, split-emit ---------------------------------
__global__ void k_dwconv_split(const float* __restrict__ in, const float* __restrict__ wt,
                               const float* __restrict__ bs,
                               uint32_t* __restrict__ Xhi, uint32_t* __restrict__ Xlo) {
    int gid = blockIdx.x * 256 + threadIdx.x;
    if (gid >= TEN / 8) return;
    int p4 = gid & 1023;
    int c2 = (gid >> 10) & 63;
    int b = gid >> 16;
    int h = p4 >> 4, w4 = (p4 & 15) * 4;

    float acc[2][4];
#pragma unroll
    for (int cc = 0; cc < 2; cc++) {
        int c = 2 * c2 + cc;
        const float* ip = in + ((size_t)b * CDIM + c) * NPIX;
        const float* wc = wt + c * 9;
        float a0 = bs[c], a1 = a0, a2 = a0, a3 = a0;
#pragma unroll
        for (int ky = 0; ky < 3; ky++) {
            int hh = h + ky - 1;
            if ((unsigned)hh < 64u) {
                const float* rp = ip + hh * 64;
                float4 cv = *(const float4*)(rp + w4);
                float lv = (w4 > 0) ? rp[w4 - 1] : 0.f;
                float rv = (w4 + 4 < 64) ? rp[w4 + 4] : 0.f;
                float w0 = wc[ky * 3 + 0], w1 = wc[ky * 3 + 1], w2 = wc[ky * 3 + 2];
                a0 += w0 * lv   + w1 * cv.x + w2 * cv.y;
                a1 += w0 * cv.x + w1 * cv.y + w2 * cv.z;
                a2 += w0 * cv.y + w1 * cv.z + w2 * cv.w;
                a3 += w0 * cv.z + w1 * cv.w + w2 * rv;
            }
        }
        acc[cc][0] = fmaxf(a0, 0.f); acc[cc][1] = fmaxf(a1, 0.f);
        acc[cc][2] = fmaxf(a2, 0.f); acc[cc][3] = fmaxf(a3, 0.f);
    }
    uint4 h4, l4;
    pack2_hi_lo(acc[0][0], acc[1][0], h4.x, l4.x);
    pack2_hi_lo(acc[0][1], acc[1][1], h4.y, l4.y);
    pack2_hi_lo(acc[0][2], acc[1][2], h4.z, l4.z);
    pack2_hi_lo(acc[0][3], acc[1][3], h4.w, l4.w);
    size_t oi = ((size_t)b * 64 + c2) * NPIX + h * 64 + w4;
    *(uint4*)(Xhi + oi) = h4;
    *(uint4*)(Xlo + oi) = l4;
}

// ---------------- GN finalize: fp32 accumulate, fp64 only at the last combine ------
__global__ void k_gnfin(const float* __restrict__ part, float* __restrict__ stats) {
    int b = blockIdx.x;
    int tid = threadIdx.x;
    __shared__ float sh[16], sh2[16];
    const float2* p = (const float2*)(part + b * 8192);
    float s = 0.f, s2 = 0.f;
#pragma unroll
    for (int i = 0; i < 16; i++) {
        float2 v = p[tid + i * 256];
        s += v.x;
        s2 += v.y;
    }
#pragma unroll
    for (int off = 16; off > 0; off >>= 1) {
        s  += __shfl_down_sync(0xffffffffu, s,  off);
        s2 += __shfl_down_sync(0xffffffffu, s2, off);
    }
    if ((tid & 31) == 0) {
        sh[tid >> 5] = s;
        sh2[tid >> 5] = s2;
    }
    __syncthreads();
    if (tid == 0) {
        double ds = 0.0, ds2 = 0.0;
#pragma unroll
        for (int w = 0; w < 8; w++) {
            ds += (double)sh[w];
            ds2 += (double)sh2[w];
        }
        double n = (double)(CDIM * NPIX);
        double mu = ds / n;
        double var = ds2 / n - mu * mu;
        stats[b] = (float)mu;
        stats[8 + b] = (float)(1.0 / sqrt(var + 1e-5));
    }
}

// ---------------- tensor-core conv1x1 GEMM (bf16x3, cp.async 3-stage) --------------
// FLAGS: bit2 RELU, bit3 ADD_RES, bit4 EMIT_SPLIT, bit5 IN_MULF, bit6 DUAL
template <int FLAGS>
__global__ void __launch_bounds__(256, 2)
k_gemm_tc(const uint32_t* __restrict__ Whig0, const uint32_t* __restrict__ Wlog0,
          const float* __restrict__ bias0,
          const uint32_t* __restrict__ Xhig, const uint32_t* __restrict__ Xlog,
          float* __restrict__ Y0, int O, int C,
          const float* __restrict__ resT,
          uint32_t* __restrict__ Uhi, uint32_t* __restrict__ Ulo,
          const float* __restrict__ Af, const float* __restrict__ Mf,
          const float* __restrict__ bias1, float* __restrict__ Y1) {
    constexpr bool ADDR = (FLAGS & 8) != 0;
    constexpr bool EMIT = (FLAGS & 16) != 0;
    constexpr bool MULF = (FLAGS & 32) != 0;
    constexpr bool DUAL = (FLAGS & 64) != 0;

    extern __shared__ uint32_t smg[];

    int tid = threadIdx.x;
    int lane = tid & 31, wid = tid >> 5;
    int warpM = wid >> 2, warpN = wid & 3;
    int g = lane >> 2, t = lane & 3;

    const uint32_t* Whig = Whig0;
    const uint32_t* Wlog = Wlog0;
    const float* bias = bias0;
    float* Y = Y0;
    bool relu_rt = (FLAGS & 4) != 0;
    int o0;
    if (DUAL) {
        if (blockIdx.y >= 2) {
            Whig += 8192; Wlog += 8192;
            bias = bias1; Y = Y1;
            relu_rt = false;
        }
        o0 = (blockIdx.y & 1) * 64;
    } else {
        o0 = blockIdx.y * 64;
    }
    int p0 = blockIdx.x * 128;
    int b = blockIdx.z;
    int c2n = C >> 1;
    int n_iter = c2n >> 4;

    const uint32_t* Xhb = Xhig ? (Xhig + (size_t)b * c2n * NPIX + p0) : nullptr;
    const uint32_t* Xlb = Xlog ? (Xlog + (size_t)b * c2n * NPIX + p0) : nullptr;

    float acc[2][4][4];
#pragma unroll
    for (int i = 0; i < 2; i++)
#pragma unroll
        for (int j = 0; j < 4; j++)
#pragma unroll
            for (int k = 0; k < 4; k++) acc[i][j][k] = 0.f;

    int wk = tid >> 4, wo = (tid & 15) * 4;
    int xk = tid >> 4, xn = (tid & 15) * 8;

    auto load_async = [&](int st, int kb2) {
        uint32_t* base = smg + st * GEMM_STAGE_U32;
        cp16(base + wk * 72 + wo,        Whig + (size_t)(kb2 + wk) * O + o0 + wo);
        cp16(base + 1152 + wk * 72 + wo, Wlog + (size_t)(kb2 + wk) * O + o0 + wo);
        const uint32_t* sh_ = Xhb + (size_t)(kb2 + xk) * NPIX + xn;
        const uint32_t* sl_ = Xlb + (size_t)(kb2 + xk) * NPIX + xn;
        cp16(base + 2304 + xk * 136 + xn,     sh_);
        cp16(base + 2304 + xk * 136 + xn + 4, sh_ + 4);
        cp16(base + 4480 + xk * 136 + xn,     sl_);
        cp16(base + 4480 + xk * 136 + xn + 4, sl_ + 4);
        asm volatile("cp.async.commit_group;");
    };

    auto load_mulf = [&](int kb2) {
        uint32_t* base = smg;
        *(uint4*)(base + wk * 72 + wo)        = *(const uint4*)(Whig + (size_t)(kb2 + wk) * O + o0 + wo);
        *(uint4*)(base + 1152 + wk * 72 + wo) = *(const uint4*)(Wlog + (size_t)(kb2 + wk) * O + o0 + wo);
        int c0 = (kb2 + xk) * 2;
        const float* a0 = Af + ((size_t)b * C + c0) * NPIX + p0 + xn;
        const float* a1 = a0 + NPIX;
        const float* m0 = Mf + ((size_t)b * C + c0) * NPIX + p0 + xn;
        const float* m1 = m0 + NPIX;
        float4 x0 = *(const float4*)(a0);
        float4 x1 = *(const float4*)(a0 + 4);
        float4 y0 = *(const float4*)(a1);
        float4 y1 = *(const float4*)(a1 + 4);
        float4 u0 = *(const float4*)(m0);
        float4 u1 = *(const float4*)(m0 + 4);
        float4 v0 = *(const float4*)(m1);
        float4 v1 = *(const float4*)(m1 + 4);
        float ra[8] = {x0.x * u0.x, x0.y * u0.y, x0.z * u0.z, x0.w * u0.w,
                       x1.x * u1.x, x1.y * u1.y, x1.z * u1.z, x1.w * u1.w};
        float rb[8] = {y0.x * v0.x, y0.y * v0.y, y0.z * v0.z, y0.w * v0.w,
                       y1.x * v1.x, y1.y * v1.y, y1.z * v1.z, y1.w * v1.w};
#pragma unroll
        for (int j = 0; j < 8; j++) {
            uint32_t hi, lo;
            pack2_hi_lo(ra[j], rb[j], hi, lo);
            base[2304 + xk * 136 + xn + j] = hi;
            base[4480 + xk * 136 + xn + j] = lo;
        }
    };

    auto compute = [&](int st) {
        uint32_t* Wh = smg + st * GEMM_STAGE_U32;
        uint32_t* Wl = Wh + 1152;
        uint32_t* Xh = Wh + 2304;
        uint32_t* Xl = Wh + 4480;
#pragma unroll
        for (int ks2 = 0; ks2 < 16; ks2 += 8) {
            uint32_t ah[2][4], al[2][4];
#pragma unroll
            for (int mt = 0; mt < 2; mt++) {
                int m0 = warpM * 32 + mt * 16;
                ah[mt][0] = Wh[(ks2 + t) * 72 + m0 + g];
                ah[mt][1] = Wh[(ks2 + t) * 72 + m0 + g + 8];
                ah[mt][2] = Wh[(ks2 + t + 4) * 72 + m0 + g];
                ah[mt][3] = Wh[(ks2 + t + 4) * 72 + m0 + g + 8];
                al[mt][0] = Wl[(ks2 + t) * 72 + m0 + g];
                al[mt][1] = Wl[(ks2 + t) * 72 + m0 + g + 8];
                al[mt][2] = Wl[(ks2 + t + 4) * 72 + m0 + g];
                al[mt][3] = Wl[(ks2 + t + 4) * 72 + m0 + g + 8];
            }
            uint32_t bh[4][2], bl[4][2];
#pragma unroll
            for (int nt = 0; nt < 4; nt++) {
                int n0 = warpN * 32 + nt * 8 + g;
                bh[nt][0] = Xh[(ks2 + t) * 136 + n0];
                bh[nt][1] = Xh[(ks2 + t + 4) * 136 + n0];
                bl[nt][0] = Xl[(ks2 + t) * 136 + n0];
                bl[nt][1] = Xl[(ks2 + t + 4) * 136 + n0];
            }
#pragma unroll
            for (int mt = 0; mt < 2; mt++)
#pragma unroll
                for (int nt = 0; nt < 4; nt++) {
                    mma_bf16(acc[mt][nt], ah[mt], bh[nt]);
                    mma_bf16(acc[mt][nt], ah[mt], bl[nt]);
                    mma_bf16(acc[mt][nt], al[mt], bh[nt]);
                }
        }
    };

    if constexpr (MULF) {
        for (int it = 0; it < n_iter; it++) {
            load_mulf(it * 16);
            __syncthreads();
            compute(0);
            __syncthreads();
        }
    } else {
        load_async(0, 0);
        if (n_iter > 1) load_async(1, 16);
        for (int it = 0; it < n_iter; it++) {
            if (it + 2 < n_iter) {
                load_async((it + 2) % 3, (it + 2) * 16);
                asm volatile("cp.async.wait_group 2;");
            } else if (it + 1 < n_iter) {
                asm volatile("cp.async.wait_group 1;");
            } else {
                asm volatile("cp.async.wait_group 0;");
            }
            __syncthreads();
            compute(it % 3);
            __syncthreads();
        }
    }

#pragma unroll
    for (int mt = 0; mt < 2; mt++) {
        int r0 = o0 + warpM * 32 + mt * 16 + g;
        int r1 = r0 + 8;
        float bi0 = bias[r0], bi1 = bias[r1];
#pragma unroll
        for (int nt = 0; nt < 4; nt++) {
            int cc = p0 + warpN * 32 + nt * 8 + t * 2;
            float v00 = acc[mt][nt][0] + bi0;
            float v01 = acc[mt][nt][1] + bi0;
            float v10 = acc[mt][nt][2] + bi1;
            float v11 = acc[mt][nt][3] + bi1;
            if (relu_rt) {
                v00 = fmaxf(v00, 0.f); v01 = fmaxf(v01, 0.f);
                v10 = fmaxf(v10, 0.f); v11 = fmaxf(v11, 0.f);
            }
            if (EMIT) {
                float p00 = __shfl_xor_sync(0xffffffffu, v00, 4);
                float p01 = __shfl_xor_sync(0xffffffffu, v01, 4);
                float p10 = __shfl_xor_sync(0xffffffffu, v10, 4);
                float p11 = __shfl_xor_sync(0xffffffffu, v11, 4);
                if ((g & 1) == 0) {
                    uint32_t h0, l0, h1, l1;
                    pack2_hi_lo(v00, p00, h0, l0);
                    pack2_hi_lo(v01, p01, h1, l1);
                    size_t oi0 = ((size_t)b * (O >> 1) + (r0 >> 1)) * NPIX + cc;
                    *(uint2*)(Uhi + oi0) = make_uint2(h0, h1);
                    *(uint2*)(Ulo + oi0) = make_uint2(l0, l1);
                    pack2_hi_lo(v10, p10, h0, l0);
                    pack2_hi_lo(v11, p11, h1, l1);
                    size_t oi1 = ((size_t)b * (O >> 1) + (r1 >> 1)) * NPIX + cc;
                    *(uint2*)(Uhi + oi1) = make_uint2(h0, h1);
                    *(uint2*)(Ulo + oi1) = make_uint2(l0, l1);
                }
            } else {
                size_t i0 = ((size_t)b * O + r0) * NPIX + cc;
                size_t i1 = ((size_t)b * O + r1) * NPIX + cc;
                if (ADDR) {
                    float2 q0 = *(const float2*)(resT + i0);
                    float2 q1 = *(const float2*)(resT + i1);
                    v00 += q0.x; v01 += q0.y; v10 += q1.x; v11 += q1.y;
                }
                *(float2*)(Y + i0) = make_float2(v00, v01);
                *(float2*)(Y + i1) = make_float2(v10, v11);
            }
        }
    }
}

// ---------------- MMA windowed attention (both variants, one launch) ---------------
// QK^T: full bf16x3 (scores feed exp). P@V: P-hi only (P rounding ~2^-9, incoherent
// over 256 keys -> O error ~1e-4 worst case, diluted by residual downstream).
__global__ void __launch_bounds__(128)
k_attn_mma(const float* __restrict__ qkv, float* __restrict__ out) {
    extern __shared__ char smem_raw[];
    uint32_t* Khi = (uint32_t*)smem_raw;
    uint32_t* Klo = Khi + 2048;
    uint32_t* Vhi = Klo + 2048;
    uint32_t* Vlo = Vhi + 2048;
    uint32_t* Qhi = Vlo + 2048;
    uint32_t* Qlo = Qhi + 2048;
    float* Osm = (float*)smem_raw;

    int tid = threadIdx.x;
    int lane = tid & 31, wrp = tid >> 5;
    int g = lane >> 2, t = lane & 3;
    int bx0 = blockIdx.x;
    int variant = bx0 >> 10;
    int bx = bx0 & 1023;
    int head = bx & 7;
    int widx = (bx >> 3) & 15;
    int b = bx >> 7;
    int qoff = variant ? 3 : 0;
    int koff = qoff + 1;

    size_t cbase = ((size_t)(b * 640 + head * 80)) * NPIX;

#pragma unroll
    for (int i = 0; i < 4; i++) {
        int gidx = tid + i * 128;
        int dp = gidx >> 6, grp = gidx & 63;
        int pix0 = (variant == 0) ? grp * 64 + widx * 4
                                  : (widx * 4 + (grp >> 4)) * 64 + (grp & 15) * 4;
        int l0 = grp * 4;
        const float* q0p = qkv + cbase + (size_t)(5 * (2 * dp) + qoff) * NPIX + pix0;
        const float* q1p = qkv + cbase + (size_t)(5 * (2 * dp + 1) + qoff) * NPIX + pix0;
        float4 qa = *(const float4*)q0p;
        float4 qb = *(const float4*)q1p;
        uint32_t hi, lo;
        pack2_hi_lo(qa.x, qb.x, hi, lo); Qhi[(l0 + 0) * 8 + dp] = hi; Qlo[(l0 + 0) * 8 + dp] = lo;
        pack2_hi_lo(qa.y, qb.y, hi, lo); Qhi[(l0 + 1) * 8 + dp] = hi; Qlo[(l0 + 1) * 8 + dp] = lo;
        pack2_hi_lo(qa.z, qb.z, hi, lo); Qhi[(l0 + 2) * 8 + dp] = hi; Qlo[(l0 + 2) * 8 + dp] = lo;
        pack2_hi_lo(qa.w, qb.w, hi, lo); Qhi[(l0 + 3) * 8 + dp] = hi; Qlo[(l0 + 3) * 8 + dp] = lo;
        const float* k0p = qkv + cbase + (size_t)(5 * (2 * dp) + koff) * NPIX + pix0;
        const float* k1p = qkv + cbase + (size_t)(5 * (2 * dp + 1) + koff) * NPIX + pix0;
        float4 ka = *(const float4*)k0p;
        float4 kb = *(const float4*)k1p;
        pack2_hi_lo(ka.x, kb.x, hi, lo); Khi[(l0 + 0) * 8 + dp] = hi; Klo[(l0 + 0) * 8 + dp] = lo;
        pack2_hi_lo(ka.y, kb.y, hi, lo); Khi[(l0 + 1) * 8 + dp] = hi; Klo[(l0 + 1) * 8 + dp] = lo;
        pack2_hi_lo(ka.z, kb.z, hi, lo); Khi[(l0 + 2) * 8 + dp] = hi; Klo[(l0 + 2) * 8 + dp] = lo;
        pack2_hi_lo(ka.w, kb.w, hi, lo); Khi[(l0 + 3) * 8 + dp] = hi; Klo[(l0 + 3) * 8 + dp] = lo;
    }
#pragma unroll
    for (int i = 0; i < 8; i++) {
        int gidx = tid + i * 128;
        int d = gidx >> 6, grp = gidx & 63;
        int pix0 = (variant == 0) ? grp * 64 + widx * 4
                                  : (widx * 4 + (grp >> 4)) * 64 + (grp & 15) * 4;
        const float* vp = qkv + cbase + (size_t)(5 * d + 2) * NPIX + pix0;
        float4 v = *(const float4*)vp;
        uint32_t hi, lo;
        pack2_hi_lo(v.x, v.y, hi, lo); Vhi[d * 128 + grp * 2] = hi;     Vlo[d * 128 + grp * 2] = lo;
        pack2_hi_lo(v.z, v.w, hi, lo); Vhi[d * 128 + grp * 2 + 1] = hi; Vlo[d * 128 + grp * 2 + 1] = lo;
    }
    __syncthreads();

    uint32_t qah[4][4], qal[4][4];
#pragma unroll
    for (int mt = 0; mt < 4; mt++) {
        int r = wrp * 64 + mt * 16 + g;
        qah[mt][0] = Qhi[r * 8 + t];       qah[mt][1] = Qhi[(r + 8) * 8 + t];
        qah[mt][2] = Qhi[r * 8 + t + 4];   qah[mt][3] = Qhi[(r + 8) * 8 + t + 4];
        qal[mt][0] = Qlo[r * 8 + t];       qal[mt][1] = Qlo[(r + 8) * 8 + t];
        qal[mt][2] = Qlo[r * 8 + t + 4];   qal[mt][3] = Qlo[(r + 8) * 8 + t + 4];
    }

    float Oa[4][2][4];
    float mrun[4][2], lrun[4][2];
#pragma unroll
    for (int mt = 0; mt < 4; mt++) {
        mrun[mt][0] = -1e30f; mrun[mt][1] = -1e30f;
        lrun[mt][0] = 0.f;    lrun[mt][1] = 0.f;
#pragma unroll
        for (int nt = 0; nt < 2; nt++)
#pragma unroll
            for (int j = 0; j < 4; j++) Oa[mt][nt][j] = 0.f;
    }

    for (int kt = 0; kt < 16; kt++) {
        int key0 = kt * 16;
        uint32_t kbh[2][2], kbl[2][2];
        {
            int kr0 = (key0 + g) * 8, kr1 = (key0 + 8 + g) * 8;
            kbh[0][0] = Khi[kr0 + t]; kbh[0][1] = Khi[kr0 + t + 4];
            kbh[1][0] = Khi[kr1 + t]; kbh[1][1] = Khi[kr1 + t + 4];
            kbl[0][0] = Klo[kr0 + t]; kbl[0][1] = Klo[kr0 + t + 4];
            kbl[1][0] = Klo[kr1 + t]; kbl[1][1] = Klo[kr1 + t + 4];
        }
        uint32_t vbh[2][2], vbl[2][2];
        {
            int kp = (key0 >> 1) + t;
            vbh[0][0] = Vhi[g * 128 + kp];        vbh[0][1] = Vhi[g * 128 + kp + 4];
            vbh[1][0] = Vhi[(g + 8) * 128 + kp];  vbh[1][1] = Vhi[(g + 8) * 128 + kp + 4];
            vbl[0][0] = Vlo[g * 128 + kp];        vbl[0][1] = Vlo[g * 128 + kp + 4];
            vbl[1][0] = Vlo[(g + 8) * 128 + kp];  vbl[1][1] = Vlo[(g + 8) * 128 + kp + 4];
        }
#pragma unroll
        for (int mt = 0; mt < 4; mt++) {
            float S[2][4];
#pragma unroll
            for (int nt = 0; nt < 2; nt++)
#pragma unroll
                for (int j = 0; j < 4; j++) S[nt][j] = 0.f;
            mma_bf16(S[0], qah[mt], kbh[0]);
            mma_bf16(S[0], qah[mt], kbl[0]);
            mma_bf16(S[0], qal[mt], kbh[0]);
            mma_bf16(S[1], qah[mt], kbh[1]);
            mma_bf16(S[1], qah[mt], kbl[1]);
            mma_bf16(S[1], qal[mt], kbh[1]);

            float mx0 = fmaxf(fmaxf(S[0][0], S[0][1]), fmaxf(S[1][0], S[1][1]));
            float mx1 = fmaxf(fmaxf(S[0][2], S[0][3]), fmaxf(S[1][2], S[1][3]));
            mx0 = fmaxf(mx0, __shfl_xor_sync(0xffffffffu, mx0, 1));
            mx0 = fmaxf(mx0, __shfl_xor_sync(0xffffffffu, mx0, 2));
            mx1 = fmaxf(mx1, __shfl_xor_sync(0xffffffffu, mx1, 1));
            mx1 = fmaxf(mx1, __shfl_xor_sync(0xffffffffu, mx1, 2));
            float mn0 = fmaxf(mrun[mt][0], mx0);
            float mn1 = fmaxf(mrun[mt][1], mx1);
            float f0 = __expf(mrun[mt][0] - mn0);
            float f1 = __expf(mrun[mt][1] - mn1);
            mrun[mt][0] = mn0; mrun[mt][1] = mn1;

            float p[2][4];
            p[0][0] = __expf(S[0][0] - mn0); p[0][1] = __expf(S[0][1] - mn0);
            p[0][2] = __expf(S[0][2] - mn1); p[0][3] = __expf(S[0][3] - mn1);
            p[1][0] = __expf(S[1][0] - mn0); p[1][1] = __expf(S[1][1] - mn0);
            p[1][2] = __expf(S[1][2] - mn1); p[1][3] = __expf(S[1][3] - mn1);

            float rs0 = p[0][0] + p[0][1] + p[1][0] + p[1][1];
            float rs1 = p[0][2] + p[0][3] + p[1][2] + p[1][3];
            rs0 += __shfl_xor_sync(0xffffffffu, rs0, 1);
            rs0 += __shfl_xor_sync(0xffffffffu, rs0, 2);
            rs1 += __shfl_xor_sync(0xffffffffu, rs1, 1);
            rs1 += __shfl_xor_sync(0xffffffffu, rs1, 2);
            lrun[mt][0] = lrun[mt][0] * f0 + rs0;
            lrun[mt][1] = lrun[mt][1] * f1 + rs1;

#pragma unroll
            for (int nt = 0; nt < 2; nt++) {
                Oa[mt][nt][0] *= f0; Oa[mt][nt][1] *= f0;
                Oa[mt][nt][2] *= f1; Oa[mt][nt][3] *= f1;
            }

            uint32_t pah[4];
            pah[0] = pack2_hi(p[0][0], p[0][1]);
            pah[1] = pack2_hi(p[0][2], p[0][3]);
            pah[2] = pack2_hi(p[1][0], p[1][1]);
            pah[3] = pack2_hi(p[1][2], p[1][3]);

            mma_bf16(Oa[mt][0], pah, vbh[0]);
            mma_bf16(Oa[mt][0], pah, vbl[0]);
            mma_bf16(Oa[mt][1], pah, vbh[1]);
            mma_bf16(Oa[mt][1], pah, vbl[1]);
        }
    }

    __syncthreads();

#pragma unroll
    for (int mt = 0; mt < 4; mt++) {
        int r = wrp * 64 + mt * 16 + g;
        float i0 = 1.f / lrun[mt][0];
        float i1 = 1.f / lrun[mt][1];
        Osm[r * 20 + 2 * t]           = Oa[mt][0][0] * i0;
        Osm[r * 20 + 2 * t + 1]       = Oa[mt][0][1] * i0;
        Osm[(r + 8) * 20 + 2 * t]     = Oa[mt][0][2] * i1;
        Osm[(r + 8) * 20 + 2 * t + 1] = Oa[mt][0][3] * i1;
        Osm[r * 20 + 8 + 2 * t]           = Oa[mt][1][0] * i0;
        Osm[r * 20 + 8 + 2 * t + 1]       = Oa[mt][1][1] * i0;
        Osm[(r + 8) * 20 + 8 + 2 * t]     = Oa[mt][1][2] * i1;
        Osm[(r + 8) * 20 + 8 + 2 * t + 1] = Oa[mt][1][3] * i1;
    }
    __syncthreads();

#pragma unroll
    for (int i = 0; i < 8; i++) {
        int gidx = tid + i * 128;
        int d = gidx >> 6, grp = gidx & 63;
        int pix0 = (variant == 0) ? grp * 64 + widx * 4
                                  : (widx * 4 + (grp >> 4)) * 64 + (grp & 15) * 4;
        int l0 = grp * 4;
        float* op = out + ((size_t)(b * 128 + head * 16 + d)) * NPIX + pix0;
        float4 cur = *(float4*)op;
        cur.x += Osm[(l0 + 0) * 20 + d];
        cur.y += Osm[(l0 + 1) * 20 + d];
        cur.z += Osm[(l0 + 2) * 20 + d];
        cur.w += Osm[(l0 + 3) * 20 + d];
        *(float4*)op = cur;
    }
}

// ---------------- orchestration ------------------------------------------------
extern "C" void kernel_launch(void* const* d_in, const int* in_sizes, int n_in,
                              void* d_out, int out_size) {
    (void)in_sizes; (void)n_in; (void)out_size;
    const float* x      = (const float*)d_in[0];
    const float* eca_w  = (const float*)d_in[1];
    const float* esa_a  = (const float*)d_in[2];
    const float* cpe1_w = (const float*)d_in[3];
    const float* cpe1_b = (const float*)d_in[4];
    const float* g1     = (const float*)d_in[5];
    const float* b1     = (const float*)d_in[6];
    const float* actp_w = (const float*)d_in[7];
    const float* actp_b = (const float*)d_in[8];
    const float* inp_w  = (const float*)d_in[9];
    const float* inp_b  = (const float*)d_in[10];
    const float* dwc_w  = (const float*)d_in[11];
    const float* dwc_b  = (const float*)d_in[12];
    const float* qkv_w  = (const float*)d_in[13];
    const float* qkv_b  = (const float*)d_in[14];
    const float* eaax_w = (const float*)d_in[15];
    const float* eaax_b = (const float*)d_in[16];
    const float* eaay_w = (const float*)d_in[17];
    const float* eaay_b = (const float*)d_in[18];
    const float* outp_w = (const float*)d_in[19];
    const float* outp_b = (const float*)d_in[20];
    const float* cpe2_w = (const float*)d_in[21];
    const float* cpe2_b = (const float*)d_in[22];
    const float* g2     = (const float*)d_in[23];
    const float* b2     = (const float*)d_in[24];
    const float* mlp1_w = (const float*)d_in[25];
    const float* mlp1_b = (const float*)d_in[26];
    const float* mlp2_w = (const float*)d_in[27];
    const float* mlp2_b = (const float*)d_in[28];
    float* out = (float*)d_out;

    float *bufA, *bufB, *bufC, *bufD, *qkv, *m, *st1, *st2, *cw, *cb, *gnp;
    uint32_t *xhi, *xlo, *yhi, *ylo, *whi, *wlo;
    cudaGetSymbolAddress((void**)&bufA, g_bufA);
    cudaGetSymbolAddress((void**)&bufB, g_bufB);
    cudaGetSymbolAddress((void**)&bufC, g_bufC);
    cudaGetSymbolAddress((void**)&bufD, g_bufD);
    cudaGetSymbolAddress((void**)&qkv,  g_qkv);
    cudaGetSymbolAddress((void**)&m,    g_m);
    cudaGetSymbolAddress((void**)&gnp,  g_gnpart);
    cudaGetSymbolAddress((void**)&st1,  g_stats1);
    cudaGetSymbolAddress((void**)&st2,  g_stats2);
    cudaGetSymbolAddress((void**)&cw,   g_cpe_w);
    cudaGetSymbolAddress((void**)&cb,   g_cpe_b);
    cudaGetSymbolAddress((void**)&xhi,  g_xhi);
    cudaGetSymbolAddress((void**)&xlo,  g_xlo);
    cudaGetSymbolAddress((void**)&yhi,  g_yhi);
    cudaGetSymbolAddress((void**)&ylo,  g_ylo);
    cudaGetSymbolAddress((void**)&whi,  g_whi);
    cudaGetSymbolAddress((void**)&wlo,  g_wlo);

    cudaFuncSetAttribute(k_attn_mma, cudaFuncAttributeMaxDynamicSharedMemorySize, ATTN_SMEM);
    cudaFuncSetAttribute(k_gemm_tc<0>,      cudaFuncAttributeMaxDynamicSharedMemorySize, GEMM_SMEM);
    cudaFuncSetAttribute(k_gemm_tc<8>,      cudaFuncAttributeMaxDynamicSharedMemorySize, GEMM_SMEM);
    cudaFuncSetAttribute(k_gemm_tc<4 | 16>, cudaFuncAttributeMaxDynamicSharedMemorySize, GEMM_SMEM);
    cudaFuncSetAttribute(k_gemm_tc<8 | 32>, cudaFuncAttributeMaxDynamicSharedMemorySize, GEMM_SMEM);
    cudaFuncSetAttribute(k_gemm_tc<4 | 64>, cudaFuncAttributeMaxDynamicSharedMemorySize, GEMM_SMEM);

    const int DW_GRID = (TEN / 4) / 256;
    const int XP128 = (BATCH * 64 * 1024) / 256;
    dim3 ggDual(32, 4, 8), gg128(32, 2, 8), gg640(32, 10, 8), gg512(32, 8, 8);

    // 0) merged prep
    k_prep<<<1537, 256>>>(actp_w, inp_w, qkv_w, outp_w, mlp1_w, mlp2_w,
                          x, m, eaax_w, eaax_b, eaay_w, eaay_b);

    // 1) eca+esa
    k_ecaesa<<<512, 256>>>(x, m, eca_w, esa_a, bufA);

    // 2) x1 = y1 + dwconv(cpe1) -> bufB = shortcut (+ fp32 warp GN partials)
    k_dwconv4<1><<<DW_GRID, 256>>>(bufA, cpe1_w, cpe1_b, bufB, 1, 1, 0, CDIM * NPIX, gnp);

    // 3) GN1 finalize (fp32 fast path) + preconvert gn(x1)
    k_gnfin<<<8, 256>>>(gnp, st1);
    k_xprep<1><<<XP128, 256>>>(bufB, nullptr, xhi, xlo, st1, g1, b1);

    // 4) DUAL GEMM: act_res / u
    k_gemm_tc<4 | 64><<<ggDual, 256, GEMM_SMEM>>>(whi + WOFF_ACTP, wlo + WOFF_ACTP, actp_b,
                                                  xhi, xlo, bufC, 128, 128,
                                                  nullptr, nullptr, nullptr, nullptr, nullptr,
                                                  inp_b, bufA);

    // 5) t = relu(dwconv(u)) -> split into xhi/xlo
    k_dwconv_split<<<(TEN / 8) / 256, 256>>>(bufA, dwc_w, dwc_b, xhi, xlo);

    // 6) qkv
    k_gemm_tc<0><<<gg640, 256, GEMM_SMEM>>>(whi + WOFF_QKV, wlo + WOFF_QKV, qkv_b, xhi, xlo, qkv, 640, 128, nullptr, nullptr, nullptr, nullptr, nullptr, nullptr, nullptr);

    // 7) cpe dwconv + both attentions
    k_dwconv4<0><<<DW_GRID, 256>>>(qkv, cw, cb, bufA, 0, 5, 2, 640 * NPIX, nullptr);
    k_attn_mma<<<2048, 128, ATTN_SMEM>>>(qkv, bufA);

    // 8) out1 = outp(a * act_res) + shortcut
    k_gemm_tc<8 | 32><<<gg128, 256, GEMM_SMEM>>>(whi + WOFF_OUTP, wlo + WOFF_OUTP, outp_b, nullptr, nullptr, bufD, 128, 128, bufB, nullptr, nullptr, bufA, bufC, nullptr, nullptr);

    // 9) out2 = out1 + dwconv(cpe2) (+ GN2 partials)
    k_dwconv4<1><<<DW_GRID, 256>>>(bufD, cpe2_w, cpe2_b, bufA, 1, 1, 0, CDIM * NPIX, gnp);

    // 10) GN2 finalize + MLP + residual
    k_gnfin<<<8, 256>>>(gnp, st2);
    k_xprep<1><<<XP128, 256>>>(bufA, nullptr, xhi, xlo, st2, g2, b2);
    k_gemm_tc<4 | 16><<<gg512, 256, GEMM_SMEM>>>(whi + WOFF_MLP1, wlo + WOFF_MLP1, mlp1_b, xhi, xlo, nullptr, 512, 128, nullptr, yhi, ylo, nullptr, nullptr, nullptr, nullptr);
    k_gemm_tc<8><<<gg128, 256, GEMM_SMEM>>>(whi + WOFF_MLP2, wlo + WOFF_MLP2, mlp2_b, yhi, ylo, out, 128, 512, bufA, nullptr, nullptr, nullptr, nullptr, nullptr, nullptr);
}